// round 13
// baseline (speedup 1.0000x reference)
#include <cuda_runtime.h>
#include <cuda_bf16.h>
#include <cstdint>

#define NN 122880      // nodes per graph
#define NE 245760      // edges per graph
#define HH 300         // hidden (logical)
#define NPS 304        // scratch row stride
#define NP 320         // weight array row count (packed; only 304 used)
#define BB 4096        // reactions
#define NODE_IN 64
#define EDGE_IN 16

// smem geometry: CTA tile 128 rows x 304 cols, 512 threads (16 warps = 8m x 2n)
#define ROWB 80
#define A_HI_OFF 0
#define A_LO_OFF (128 * ROWB)                  // 10240
#define B_HI_OFF (2 * 128 * ROWB)              // 20480
#define B_LO_OFF (B_HI_OFF + 304 * ROWB)       // 44800
#define BUFSTRIDE (B_LO_OFF + 304 * ROWB)      // 69120
#define SMEM_BYTES (2 * BUFSTRIDE)             // 138240

// ---- scratch (device globals; no allocations allowed) ----
__device__ float g_h [3][(size_t)NN * NPS];
__device__ float g_ef[3][(size_t)NE * NPS];
__device__ float g_z [3][(size_t)NN * NPS];
__device__ float g_t [3][(size_t)NN * NPS];
__device__ __nv_bfloat16 g_Wnhi[(size_t)NP * 64];
__device__ __nv_bfloat16 g_Wnlo[(size_t)NP * 64];
__device__ __nv_bfloat16 g_Wehi[(size_t)NP * 32];
__device__ __nv_bfloat16 g_Welo[(size_t)NP * 32];
__device__ __nv_bfloat16 g_W1hi[(size_t)3 * NP * 320];
__device__ __nv_bfloat16 g_W1lo[(size_t)3 * NP * 320];
__device__ __nv_bfloat16 g_W2hi[(size_t)3 * NP * 320];
__device__ __nv_bfloat16 g_W2lo[(size_t)3 * NP * 320];
__device__ float g_biasp[(size_t)8 * NP];

// ============================ PTX helpers ============================
__device__ __forceinline__ uint32_t smem_u32(const void* p) {
    uint32_t a;
    asm("{ .reg .u64 t; cvta.to.shared.u64 t, %1; cvt.u32.u64 %0, t; }"
        : "=r"(a) : "l"(p));
    return a;
}
__device__ __forceinline__ void cp16(uint32_t dst, const void* src) {
    asm volatile("cp.async.cg.shared.global [%0], [%1], 16;"
                 :: "r"(dst), "l"(src) : "memory");
}
#define CP_COMMIT() asm volatile("cp.async.commit_group;" ::: "memory")

#define LDSM4(r, addr) \
    asm volatile("ldmatrix.sync.aligned.m8n8.x4.shared.b16 {%0,%1,%2,%3}, [%4];" \
        : "=r"((r)[0]), "=r"((r)[1]), "=r"((r)[2]), "=r"((r)[3]) : "r"(addr))
#define LDSM2(r, addr) \
    asm volatile("ldmatrix.sync.aligned.m8n8.x2.shared.b16 {%0,%1}, [%2];" \
        : "=r"((r)[0]), "=r"((r)[1]) : "r"(addr))

#define MMAB(d, a, b0, b1) \
    asm volatile("mma.sync.aligned.m16n8k16.row.col.f32.bf16.bf16.f32 " \
        "{%0,%1,%2,%3}, {%4,%5,%6,%7}, {%8,%9}, {%0,%1,%2,%3};" \
        : "+f"((d)[0]), "+f"((d)[1]), "+f"((d)[2]), "+f"((d)[3]) \
        : "r"((a)[0]), "r"((a)[1]), "r"((a)[2]), "r"((a)[3]), \
          "r"(b0), "r"(b1))

#define REDV4(addr, a, b, c, d) \
    asm volatile("red.global.add.v4.f32 [%0], {%1,%2,%3,%4};" \
        :: "l"(addr), "f"(a), "f"(b), "f"(c), "f"(d) : "memory")

// split x,y into packed bf16x2 (hi, lo)
__device__ __forceinline__ void split_pack(float x, float y, uint32_t& hi, uint32_t& lo) {
    __nv_bfloat16 hx = __float2bfloat16_rn(x);
    __nv_bfloat16 hy = __float2bfloat16_rn(y);
    __nv_bfloat16 lx = __float2bfloat16_rn(x - __bfloat162float(hx));
    __nv_bfloat16 ly = __float2bfloat16_rn(y - __bfloat162float(hy));
    hi = (uint32_t)__bfloat16_as_ushort(hx) | ((uint32_t)__bfloat16_as_ushort(hy) << 16);
    lo = (uint32_t)__bfloat16_as_ushort(lx) | ((uint32_t)__bfloat16_as_ushort(ly) << 16);
}

// ============================ bf16-split tensor GEMM ============================
// C tile = 128 rows x 304 cols; grid.x = M/128; 16 warps (8m x 2n), warp = 16 x 152.
__global__ __launch_bounds__(512, 1) void gemm_tc(
    const float* __restrict__ A,
    const __nv_bfloat16* __restrict__ Whi, const __nv_bfloat16* __restrict__ Wlo,
    const float* __restrict__ biasp, float* __restrict__ C,
    float* __restrict__ C2, int lda, int Kact, int kchunks, int doRelu)
{
    extern __shared__ char smem[];
    const uint32_t sb = smem_u32(smem);
    const int tid  = threadIdx.x;
    const int wid  = tid >> 5;
    const int lane = tid & 31;
    const int wm   = wid & 7;          // m eighth (16 rows)
    const int wn   = wid >> 3;         // n half (152 cols)
    const size_t rowBase = (size_t)blockIdx.x * 128;
    const int Kp = kchunks * 32;
    const bool skipKs1 = (Kact - (kchunks - 1) * 32) <= 16;

    const int lr = lane & 7;
    const int g  = lane >> 3;
    const uint32_t aoff = ((uint32_t)(wm * 16 + lr + (g & 1) * 8)) * ROWB + ((g >> 1) << 4);
    const uint32_t boff = ((uint32_t)(wn * 152 + lr + (g >> 1) * 8)) * ROWB + ((g & 1) << 4);
    const uint32_t boff2 = ((uint32_t)(wn * 152 + 144 + lr)) * ROWB + ((g & 1) << 4);

    float acc[19][4];
#pragma unroll
    for (int j = 0; j < 19; j++)
#pragma unroll
        for (int q = 0; q < 4; q++) acc[j][q] = 0.f;

    float4 pre[2];
    auto ldg_regs = [&](int cidx) {
        const int k0 = cidx * 32;
#pragma unroll
        for (int i = 0; i < 2; ++i) {
            const int flat = tid + i * 512;
            const int r = flat >> 3;
            const int j = flat & 7;
            const int k = k0 + (j << 2);
            pre[i] = (k < Kact) ? *(const float4*)(A + (rowBase + r) * lda + k)
                                : make_float4(0.f, 0.f, 0.f, 0.f);
        }
    };
    auto sts_regs = [&](int cidx) {
        char* base = smem + (cidx & 1) * BUFSTRIDE;
#pragma unroll
        for (int i = 0; i < 2; ++i) {
            const int flat = tid + i * 512;
            const int r = flat >> 3;
            const int j = flat & 7;
            uint2 hi, lo;
            split_pack(pre[i].x, pre[i].y, hi.x, lo.x);
            split_pack(pre[i].z, pre[i].w, hi.y, lo.y);
            const uint32_t o = (uint32_t)r * ROWB + j * 8;
            *(uint2*)(base + A_HI_OFF + o) = hi;
            *(uint2*)(base + A_LO_OFF + o) = lo;
        }
    };
    auto cp_B = [&](int cidx) {
        const uint32_t base = sb + (cidx & 1) * BUFSTRIDE;
        const int k0 = cidx * 32;
#pragma unroll
        for (int i = 0; i < 5; ++i) {
            const int flat = tid + i * 512;
            if (flat < 2432) {
                const int j = flat & 3;
                const int idx = flat >> 2;              // 0..607
                const int isLo = idx >= 304;
                const int n = isLo ? idx - 304 : idx;
                const __nv_bfloat16* src =
                    (isLo ? Wlo : Whi) + (size_t)n * Kp + k0 + j * 8;
                const uint32_t dst = base + (isLo ? B_LO_OFF : B_HI_OFF)
                                   + (uint32_t)n * ROWB + j * 16;
                cp16(dst, src);
            }
        }
        CP_COMMIT();
    };

    // prologue
    ldg_regs(0);
    sts_regs(0);
    cp_B(0);
    if (kchunks > 1) { cp_B(1); ldg_regs(1); }

    for (int c = 0; c < kchunks; ++c) {
        if (c + 1 < kchunks) asm volatile("cp.async.wait_group 1;" ::: "memory");
        else                 asm volatile("cp.async.wait_group 0;" ::: "memory");
        __syncthreads();

        if (c + 1 < kchunks) sts_regs(c + 1);
        if (c + 2 < kchunks) ldg_regs(c + 2);

        const uint32_t base = sb + (c & 1) * BUFSTRIDE;
#pragma unroll
        for (int ks = 0; ks < 2; ++ks) {
            if (ks == 1 && skipKs1 && c == kchunks - 1) continue;
            const uint32_t kb = ks << 5;
            uint32_t ah[4], al[4];
            LDSM4(ah, base + A_HI_OFF + aoff + kb);
            LDSM4(al, base + A_LO_OFF + aoff + kb);
#pragma unroll
            for (int ntp = 0; ntp < 9; ++ntp) {
                uint32_t bh[4], bl[4];
                const uint32_t bo = boff + (uint32_t)ntp * (16 * ROWB) + kb;
                LDSM4(bh, base + B_HI_OFF + bo);
                LDSM4(bl, base + B_LO_OFF + bo);
                MMAB(acc[2 * ntp],     al, bh[0], bh[1]);
                MMAB(acc[2 * ntp + 1], al, bh[2], bh[3]);
                MMAB(acc[2 * ntp],     ah, bl[0], bl[1]);
                MMAB(acc[2 * ntp + 1], ah, bl[2], bl[3]);
                MMAB(acc[2 * ntp],     ah, bh[0], bh[1]);
                MMAB(acc[2 * ntp + 1], ah, bh[2], bh[3]);
            }
            uint32_t b2h[2], b2l[2];
            LDSM2(b2h, base + B_HI_OFF + boff2 + kb);
            LDSM2(b2l, base + B_LO_OFF + boff2 + kb);
            MMAB(acc[18], al, b2h[0], b2h[1]);
            MMAB(acc[18], ah, b2l[0], b2l[1]);
            MMAB(acc[18], ah, b2h[0], b2h[1]);
        }
        __syncthreads();
        if (c + 2 < kchunks) cp_B(c + 2);
    }

    // ---------- epilogue: bias + relu, direct float2 stores ----------
    const int colq = (lane & 3) * 2;
    const int rquad = lane >> 2;
    const size_t row0 = rowBase + wm * 16 + rquad;
#pragma unroll
    for (int nt = 0; nt < 19; ++nt) {
        const int col = wn * 152 + nt * 8 + colq;      // always < 304
        const float2 bv = *(const float2*)(biasp + col);
        float2 v01, v23;
        v01.x = acc[nt][0] + bv.x;
        v01.y = acc[nt][1] + bv.y;
        v23.x = acc[nt][2] + bv.x;
        v23.y = acc[nt][3] + bv.y;
        if (doRelu) {
            v01.x = fmaxf(v01.x, 0.f); v01.y = fmaxf(v01.y, 0.f);
            v23.x = fmaxf(v23.x, 0.f); v23.y = fmaxf(v23.y, 0.f);
        }
        const size_t o0 = row0 * NPS + col;
        const size_t o1 = (row0 + 8) * NPS + col;
        *(float2*)(C + o0) = v01;
        *(float2*)(C + o1) = v23;
        if (C2) {
            *(float2*)(C2 + o0) = v01;
            *(float2*)(C2 + o1) = v23;
        }
    }
}

// ============ fused prepack: weights + biases + out zero ============
#define SZ_N (NP * 64)
#define SZ_E (NP * 32)
#define SZ_M (NP * 320)
#define PACK_W (SZ_N + SZ_E + 6 * SZ_M + 8 * NP)
#define PACK_TOTAL (PACK_W + 2 * BB * HH)

__global__ __launch_bounds__(256) void pack_all_kernel(
    const float* __restrict__ Wn, const float* __restrict__ We,
    const float* __restrict__ W1, const float* __restrict__ W2,
    const float* __restrict__ bn, const float* __restrict__ be,
    const float* __restrict__ b1, const float* __restrict__ b2,
    float* __restrict__ outAcc)
{
    int idx = blockIdx.x * 256 + threadIdx.x;
    if (idx >= PACK_TOTAL) return;
    if (idx >= PACK_W) {                  // zero r_sum/p_sum region
        outAcc[idx - PACK_W] = 0.f;
        return;
    }

    const float* W; __nv_bfloat16 *Whi, *Wlo; int Kin, Kp;
    if (idx < SZ_N) {
        W = Wn; Whi = g_Wnhi; Wlo = g_Wnlo; Kin = NODE_IN; Kp = 64;
    } else if ((idx -= SZ_N) < SZ_E) {
        W = We; Whi = g_Wehi; Wlo = g_Welo; Kin = EDGE_IN; Kp = 32;
    } else if ((idx -= SZ_E) < 3 * SZ_M) {
        const int l = idx / SZ_M; idx -= l * SZ_M;
        W = W1 + (size_t)l * HH * HH;
        Whi = g_W1hi + (size_t)l * SZ_M; Wlo = g_W1lo + (size_t)l * SZ_M;
        Kin = HH; Kp = 320;
    } else if ((idx -= 3 * SZ_M) < 3 * SZ_M) {
        const int l = idx / SZ_M; idx -= l * SZ_M;
        W = W2 + (size_t)l * HH * HH;
        Whi = g_W2hi + (size_t)l * SZ_M; Wlo = g_W2lo + (size_t)l * SZ_M;
        Kin = HH; Kp = 320;
    } else {
        idx -= 3 * SZ_M;
        const int which = idx / NP;
        const int n = idx - which * NP;
        const float* src = (which == 0) ? bn
                         : (which == 1) ? be
                         : (which < 5)  ? b1 + (size_t)(which - 2) * HH
                                        : b2 + (size_t)(which - 5) * HH;
        g_biasp[idx] = (n < HH) ? src[n] : 0.f;
        return;
    }
    const int n = idx / Kp;
    const int k = idx - n * Kp;
    float v = 0.f;
    if (k < Kin && n < HH) v = W[(size_t)k * HH + n];
    __nv_bfloat16 h = __float2bfloat16_rn(v);
    Whi[idx] = h;
    Wlo[idx] = __float2bfloat16_rn(v - __bfloat162float(h));
}

// ============ message: z[dst] += relu(h[src] + ef), thread = edge x 8 cols ============
__global__ __launch_bounds__(128) void message_kernel(
    const float* __restrict__ h, const float* __restrict__ ef,
    const int* __restrict__ src, const int* __restrict__ dst,
    float* __restrict__ z)
{
    const int idx = blockIdx.x * 128 + threadIdx.x;
    if (idx >= NE * 38) return;
    const int e = idx / 38;
    const int q = (idx - e * 38) << 3;
    const int s = __ldg(src + e);
    const int d = __ldg(dst + e);
    const float4* hp = (const float4*)(h + (size_t)s * NPS + q);
    const float4* ep = (const float4*)(ef + (size_t)e * NPS + q);
    const float4 h0 = hp[0], h1 = hp[1];
    const float4 e0 = ep[0], e1 = ep[1];
    float* zp = z + (size_t)d * NPS + q;
    const float m0 = fmaxf(h0.x + e0.x, 0.f);
    const float m1 = fmaxf(h0.y + e0.y, 0.f);
    const float m2 = fmaxf(h0.z + e0.z, 0.f);
    const float m3 = fmaxf(h0.w + e0.w, 0.f);
    if (m0 + m1 + m2 + m3 > 0.f) REDV4(zp, m0, m1, m2, m3);
    const float m4 = fmaxf(h1.x + e1.x, 0.f);
    const float m5 = fmaxf(h1.y + e1.y, 0.f);
    const float m6 = fmaxf(h1.z + e1.z, 0.f);
    const float m7 = fmaxf(h1.w + e1.w, 0.f);
    if (m4 + m5 + m6 + m7 > 0.f) REDV4(zp + 4, m4, m5, m6, m7);
}

// ============ pool: out[seg[n]] += h[n] — run-compressed atomics ============
__global__ __launch_bounds__(128) void pool_kernel(
    const float* __restrict__ h, const int* __restrict__ seg,
    float* __restrict__ out)
{
    const int wid  = threadIdx.x >> 5;
    const int lane = threadIdx.x & 31;
    const int n0   = (blockIdx.x * 4 + wid) * 32;
    const int col  = blockIdx.y * 32 + lane;
    const bool act = col < HH;

    float v[32];
    int   sg[32];
#pragma unroll
    for (int i = 0; i < 32; ++i) {
        v[i]  = act ? __ldg(h + (size_t)(n0 + i) * NPS + col) : 0.f;
        sg[i] = __ldg(seg + n0 + i);
    }
    float acc = 0.f;
#pragma unroll
    for (int i = 0; i < 32; ++i) {
        acc += v[i];
        if ((i == 31) || (sg[i + 1 <= 31 ? i + 1 : 31] != sg[i])) {
            if (act) atomicAdd(out + (size_t)sg[i] * HH + col, acc);
            acc = 0.f;
        }
    }
}

__global__ __launch_bounds__(256) void diff_kernel(float* __restrict__ out)
{
    const int idx = blockIdx.x * blockDim.x + threadIdx.x;
    const int BH = BB * HH;
    if (idx < BH) out[idx] = out[BH + idx] - out[2 * BH + idx];
}

// ============================== host orchestration ==============================
static void run_gin(cudaStream_t st, int si,
                    const float* x, const float* e,
                    const int* src, const int* dst, const int* seg,
                    __nv_bfloat16* Wnhi, __nv_bfloat16* Wnlo,
                    __nv_bfloat16* Wehi, __nv_bfloat16* Welo,
                    __nv_bfloat16* W1hi, __nv_bfloat16* W1lo,
                    __nv_bfloat16* W2hi, __nv_bfloat16* W2lo,
                    float* biasp,
                    float* hB, float* efB, float* zB, float* tB,
                    float* outPart, cudaEvent_t evProj)
{
    float* h  = hB  + (size_t)si * NN * NPS;
    float* ef = efB + (size_t)si * NE * NPS;
    float* z  = zB  + (size_t)si * NN * NPS;
    float* t  = tB  + (size_t)si * NN * NPS;

    gemm_tc<<<NN / 128, 512, SMEM_BYTES, st>>>(x, Wnhi, Wnlo, biasp, h, z,
                                               NODE_IN, NODE_IN, 2, 1);
    gemm_tc<<<NE / 128, 512, SMEM_BYTES, st>>>(e, Wehi, Welo, biasp + NP, ef, nullptr,
                                               EDGE_IN, EDGE_IN, 1, 0);
    if (evProj) cudaEventRecord(evProj, st);   // chained stagger point

    for (int l = 0; l < 3; l++) {
        message_kernel<<<NE * 38 / 128, 128, 0, st>>>(h, ef, src, dst, z);
        gemm_tc<<<NN / 128, 512, SMEM_BYTES, st>>>(
            z, W1hi + (size_t)l * NP * 320, W1lo + (size_t)l * NP * 320,
            biasp + (size_t)(2 + l) * NP, t, nullptr, NPS, NPS, 10, 1);
        gemm_tc<<<NN / 128, 512, SMEM_BYTES, st>>>(
            t, W2hi + (size_t)l * NP * 320, W2lo + (size_t)l * NP * 320,
            biasp + (size_t)(5 + l) * NP, h, (l < 2) ? z : nullptr,
            NPS, NPS, 10, (l < 2) ? 1 : 0);
    }
    const dim3 gP(NN / 32 / 4, 10);
    pool_kernel<<<gP, 128, 0, st>>>(h, seg, outPart);
}

extern "C" void kernel_launch(void* const* d_in, const int* in_sizes, int n_in,
                              void* d_out, int out_size)
{
    const float* r_x = (const float*)d_in[0];
    const float* r_e = (const float*)d_in[1];
    const float* p_x = (const float*)d_in[2];
    const float* p_e = (const float*)d_in[3];
    const float* Wn  = (const float*)d_in[4];
    const float* bn  = (const float*)d_in[5];
    const float* We  = (const float*)d_in[6];
    const float* be  = (const float*)d_in[7];
    const float* W1  = (const float*)d_in[8];
    const float* b1  = (const float*)d_in[9];
    const float* W2  = (const float*)d_in[10];
    const float* b2  = (const float*)d_in[11];
    const int* r_src = (const int*)d_in[12];
    const int* r_dst = (const int*)d_in[13];
    const int* r_seg = (const int*)d_in[14];
    const int* p_src = (const int*)d_in[15];
    const int* p_dst = (const int*)d_in[16];
    const int* p_seg = (const int*)d_in[17];

    float* out   = (float*)d_out;
    float* r_sum = out + (size_t)BB * HH;
    float* p_sum = out + (size_t)2 * BB * HH;

    float *h, *ef, *z, *t, *biasp;
    __nv_bfloat16 *Wnhi, *Wnlo, *Wehi, *Welo, *W1hi, *W1lo, *W2hi, *W2lo;
    cudaGetSymbolAddress((void**)&h,    g_h);
    cudaGetSymbolAddress((void**)&ef,   g_ef);
    cudaGetSymbolAddress((void**)&z,    g_z);
    cudaGetSymbolAddress((void**)&t,    g_t);
    cudaGetSymbolAddress((void**)&Wnhi, g_Wnhi);
    cudaGetSymbolAddress((void**)&Wnlo, g_Wnlo);
    cudaGetSymbolAddress((void**)&Wehi, g_Wehi);
    cudaGetSymbolAddress((void**)&Welo, g_Welo);
    cudaGetSymbolAddress((void**)&W1hi, g_W1hi);
    cudaGetSymbolAddress((void**)&W1lo, g_W1lo);
    cudaGetSymbolAddress((void**)&W2hi, g_W2hi);
    cudaGetSymbolAddress((void**)&W2lo, g_W2lo);
    cudaGetSymbolAddress((void**)&biasp, g_biasp);

    // one-time resources (streams/events; no device memory)
    static cudaStream_t s1 = nullptr, s2 = nullptr;
    static cudaEvent_t evP0 = nullptr, evP1 = nullptr, ev1 = nullptr, ev2 = nullptr;
    if (!s1) {
        cudaStreamCreateWithFlags(&s1, cudaStreamNonBlocking);
        cudaStreamCreateWithFlags(&s2, cudaStreamNonBlocking);
        cudaEventCreateWithFlags(&evP0, cudaEventDisableTiming);
        cudaEventCreateWithFlags(&evP1, cudaEventDisableTiming);
        cudaEventCreateWithFlags(&ev1, cudaEventDisableTiming);
        cudaEventCreateWithFlags(&ev2, cudaEventDisableTiming);
        cudaFuncSetAttribute(gemm_tc, cudaFuncAttributeMaxDynamicSharedMemorySize,
                             SMEM_BYTES);
    }

    // launch 0 (capture stream): fused prepack + zero of r_sum/p_sum
    pack_all_kernel<<<(PACK_TOTAL + 255) / 256, 256>>>(Wn, We, W1, W2,
                                                       bn, be, b1, b2, r_sum);

    // r0 on capture stream; records evP0 after its projections (~150us in)
    run_gin((cudaStream_t)0, 0,
            r_x, r_e, r_src, r_dst, r_seg,
            Wnhi, Wnlo, Wehi, Welo, W1hi, W1lo, W2hi, W2lo, biasp,
            h, ef, z, t, r_sum, evP0);

    // chained stagger: s1 starts after r0's projections; s2 after s1's projections
    cudaStreamWaitEvent(s1, evP0, 0);
    run_gin(s1, 1,
            r_x + (size_t)NN * NODE_IN, r_e + (size_t)NE * EDGE_IN,
            r_src + NE, r_dst + NE, r_seg + NN,
            Wnhi, Wnlo, Wehi, Welo, W1hi, W1lo, W2hi, W2lo, biasp,
            h, ef, z, t, r_sum, evP1);

    cudaStreamWaitEvent(s2, evP1, 0);
    run_gin(s2, 2,
            p_x, p_e, p_src, p_dst, p_seg,
            Wnhi, Wnlo, Wehi, Welo, W1hi, W1lo, W2hi, W2lo, biasp,
            h, ef, z, t, p_sum, nullptr);

    // join: diff waits on all three
    cudaEventRecord(ev1, s1);
    cudaEventRecord(ev2, s2);
    cudaStreamWaitEvent((cudaStream_t)0, ev1, 0);
    cudaStreamWaitEvent((cudaStream_t)0, ev2, 0);

    diff_kernel<<<(BB * HH + 255) / 256, 256>>>(out);
}

// round 14
// speedup vs baseline: 1.0395x; 1.0395x over previous
#include <cuda_runtime.h>
#include <cuda_bf16.h>
#include <cuda_fp16.h>
#include <cstdint>

#define NN 122880      // nodes per graph
#define NE 245760      // edges per graph
#define HH 300         // hidden (logical)
#define NPS 304        // scratch row stride
#define NP 320         // weight array row count (packed; only 304 used)
#define BB 4096        // reactions
#define NODE_IN 64
#define EDGE_IN 16

// smem geometry: CTA tile 128 rows x 304 cols, 512 threads (16 warps = 8m x 2n)
#define ROWB 80
#define A_HI_OFF 0
#define A_LO_OFF (128 * ROWB)                  // 10240
#define B_HI_OFF (2 * 128 * ROWB)              // 20480
#define B_LO_OFF (B_HI_OFF + 304 * ROWB)       // 44800
#define BUFSTRIDE (B_LO_OFF + 304 * ROWB)      // 69120
#define SMEM_BYTES (2 * BUFSTRIDE)             // 138240

// ---- scratch (device globals; no allocations allowed) ----
__device__ float  g_h [3][(size_t)NN * NPS];
__device__ __half g_ef[3][(size_t)NE * NPS];   // fp16 edge features (read 3x, written 1x)
__device__ float  g_z [3][(size_t)NN * NPS];
__device__ float  g_t [3][(size_t)NN * NPS];
__device__ __nv_bfloat16 g_Wnhi[(size_t)NP * 64];
__device__ __nv_bfloat16 g_Wnlo[(size_t)NP * 64];
__device__ __nv_bfloat16 g_Wehi[(size_t)NP * 32];
__device__ __nv_bfloat16 g_Welo[(size_t)NP * 32];
__device__ __nv_bfloat16 g_W1hi[(size_t)3 * NP * 320];
__device__ __nv_bfloat16 g_W1lo[(size_t)3 * NP * 320];
__device__ __nv_bfloat16 g_W2hi[(size_t)3 * NP * 320];
__device__ __nv_bfloat16 g_W2lo[(size_t)3 * NP * 320];
__device__ float g_biasp[(size_t)8 * NP];

// ============================ PTX helpers ============================
__device__ __forceinline__ uint32_t smem_u32(const void* p) {
    uint32_t a;
    asm("{ .reg .u64 t; cvta.to.shared.u64 t, %1; cvt.u32.u64 %0, t; }"
        : "=r"(a) : "l"(p));
    return a;
}
__device__ __forceinline__ void cp16(uint32_t dst, const void* src) {
    asm volatile("cp.async.cg.shared.global [%0], [%1], 16;"
                 :: "r"(dst), "l"(src) : "memory");
}
#define CP_COMMIT() asm volatile("cp.async.commit_group;" ::: "memory")

#define LDSM4(r, addr) \
    asm volatile("ldmatrix.sync.aligned.m8n8.x4.shared.b16 {%0,%1,%2,%3}, [%4];" \
        : "=r"((r)[0]), "=r"((r)[1]), "=r"((r)[2]), "=r"((r)[3]) : "r"(addr))
#define LDSM2(r, addr) \
    asm volatile("ldmatrix.sync.aligned.m8n8.x2.shared.b16 {%0,%1}, [%2];" \
        : "=r"((r)[0]), "=r"((r)[1]) : "r"(addr))

#define MMAB(d, a, b0, b1) \
    asm volatile("mma.sync.aligned.m16n8k16.row.col.f32.bf16.bf16.f32 " \
        "{%0,%1,%2,%3}, {%4,%5,%6,%7}, {%8,%9}, {%0,%1,%2,%3};" \
        : "+f"((d)[0]), "+f"((d)[1]), "+f"((d)[2]), "+f"((d)[3]) \
        : "r"((a)[0]), "r"((a)[1]), "r"((a)[2]), "r"((a)[3]), \
          "r"(b0), "r"(b1))

#define REDV4(addr, a, b, c, d) \
    asm volatile("red.global.add.v4.f32 [%0], {%1,%2,%3,%4};" \
        :: "l"(addr), "f"(a), "f"(b), "f"(c), "f"(d) : "memory")

// split x,y into packed bf16x2 (hi, lo)
__device__ __forceinline__ void split_pack(float x, float y, uint32_t& hi, uint32_t& lo) {
    __nv_bfloat16 hx = __float2bfloat16_rn(x);
    __nv_bfloat16 hy = __float2bfloat16_rn(y);
    __nv_bfloat16 lx = __float2bfloat16_rn(x - __bfloat162float(hx));
    __nv_bfloat16 ly = __float2bfloat16_rn(y - __bfloat162float(hy));
    hi = (uint32_t)__bfloat16_as_ushort(hx) | ((uint32_t)__bfloat16_as_ushort(hy) << 16);
    lo = (uint32_t)__bfloat16_as_ushort(lx) | ((uint32_t)__bfloat16_as_ushort(ly) << 16);
}

// ============================ bf16-split tensor GEMM ============================
// C tile = 128 rows x 304 cols; grid.x = M/128; 16 warps (8m x 2n), warp = 16 x 152.
// outHalf: store C as fp16 (used for edge features)
__global__ __launch_bounds__(512, 1) void gemm_tc(
    const float* __restrict__ A,
    const __nv_bfloat16* __restrict__ Whi, const __nv_bfloat16* __restrict__ Wlo,
    const float* __restrict__ biasp, float* __restrict__ C,
    float* __restrict__ C2, int lda, int Kact, int kchunks, int doRelu, int outHalf)
{
    extern __shared__ char smem[];
    const uint32_t sb = smem_u32(smem);
    const int tid  = threadIdx.x;
    const int wid  = tid >> 5;
    const int lane = tid & 31;
    const int wm   = wid & 7;          // m eighth (16 rows)
    const int wn   = wid >> 3;         // n half (152 cols)
    const size_t rowBase = (size_t)blockIdx.x * 128;
    const int Kp = kchunks * 32;
    const bool skipKs1 = (Kact - (kchunks - 1) * 32) <= 16;

    const int lr = lane & 7;
    const int g  = lane >> 3;
    const uint32_t aoff = ((uint32_t)(wm * 16 + lr + (g & 1) * 8)) * ROWB + ((g >> 1) << 4);
    const uint32_t boff = ((uint32_t)(wn * 152 + lr + (g >> 1) * 8)) * ROWB + ((g & 1) << 4);
    const uint32_t boff2 = ((uint32_t)(wn * 152 + 144 + lr)) * ROWB + ((g & 1) << 4);

    float acc[19][4];
#pragma unroll
    for (int j = 0; j < 19; j++)
#pragma unroll
        for (int q = 0; q < 4; q++) acc[j][q] = 0.f;

    float4 pre[2];
    auto ldg_regs = [&](int cidx) {
        const int k0 = cidx * 32;
#pragma unroll
        for (int i = 0; i < 2; ++i) {
            const int flat = tid + i * 512;
            const int r = flat >> 3;
            const int j = flat & 7;
            const int k = k0 + (j << 2);
            pre[i] = (k < Kact) ? *(const float4*)(A + (rowBase + r) * lda + k)
                                : make_float4(0.f, 0.f, 0.f, 0.f);
        }
    };
    auto sts_regs = [&](int cidx) {
        char* base = smem + (cidx & 1) * BUFSTRIDE;
#pragma unroll
        for (int i = 0; i < 2; ++i) {
            const int flat = tid + i * 512;
            const int r = flat >> 3;
            const int j = flat & 7;
            uint2 hi, lo;
            split_pack(pre[i].x, pre[i].y, hi.x, lo.x);
            split_pack(pre[i].z, pre[i].w, hi.y, lo.y);
            const uint32_t o = (uint32_t)r * ROWB + j * 8;
            *(uint2*)(base + A_HI_OFF + o) = hi;
            *(uint2*)(base + A_LO_OFF + o) = lo;
        }
    };
    auto cp_B = [&](int cidx) {
        const uint32_t base = sb + (cidx & 1) * BUFSTRIDE;
        const int k0 = cidx * 32;
#pragma unroll
        for (int i = 0; i < 5; ++i) {
            const int flat = tid + i * 512;
            if (flat < 2432) {
                const int j = flat & 3;
                const int idx = flat >> 2;              // 0..607
                const int isLo = idx >= 304;
                const int n = isLo ? idx - 304 : idx;
                const __nv_bfloat16* src =
                    (isLo ? Wlo : Whi) + (size_t)n * Kp + k0 + j * 8;
                const uint32_t dst = base + (isLo ? B_LO_OFF : B_HI_OFF)
                                   + (uint32_t)n * ROWB + j * 16;
                cp16(dst, src);
            }
        }
        CP_COMMIT();
    };

    // prologue
    ldg_regs(0);
    sts_regs(0);
    cp_B(0);
    if (kchunks > 1) { cp_B(1); ldg_regs(1); }

    for (int c = 0; c < kchunks; ++c) {
        if (c + 1 < kchunks) asm volatile("cp.async.wait_group 1;" ::: "memory");
        else                 asm volatile("cp.async.wait_group 0;" ::: "memory");
        __syncthreads();

        if (c + 1 < kchunks) sts_regs(c + 1);
        if (c + 2 < kchunks) ldg_regs(c + 2);

        const uint32_t base = sb + (c & 1) * BUFSTRIDE;
#pragma unroll
        for (int ks = 0; ks < 2; ++ks) {
            if (ks == 1 && skipKs1 && c == kchunks - 1) continue;
            const uint32_t kb = ks << 5;
            uint32_t ah[4], al[4];
            LDSM4(ah, base + A_HI_OFF + aoff + kb);
            LDSM4(al, base + A_LO_OFF + aoff + kb);
#pragma unroll
            for (int ntp = 0; ntp < 9; ++ntp) {
                uint32_t bh[4], bl[4];
                const uint32_t bo = boff + (uint32_t)ntp * (16 * ROWB) + kb;
                LDSM4(bh, base + B_HI_OFF + bo);
                LDSM4(bl, base + B_LO_OFF + bo);
                MMAB(acc[2 * ntp],     al, bh[0], bh[1]);
                MMAB(acc[2 * ntp + 1], al, bh[2], bh[3]);
                MMAB(acc[2 * ntp],     ah, bl[0], bl[1]);
                MMAB(acc[2 * ntp + 1], ah, bl[2], bl[3]);
                MMAB(acc[2 * ntp],     ah, bh[0], bh[1]);
                MMAB(acc[2 * ntp + 1], ah, bh[2], bh[3]);
            }
            uint32_t b2h[2], b2l[2];
            LDSM2(b2h, base + B_HI_OFF + boff2 + kb);
            LDSM2(b2l, base + B_LO_OFF + boff2 + kb);
            MMAB(acc[18], al, b2h[0], b2h[1]);
            MMAB(acc[18], ah, b2l[0], b2l[1]);
            MMAB(acc[18], ah, b2h[0], b2h[1]);
        }
        __syncthreads();
        if (c + 2 < kchunks) cp_B(c + 2);
    }

    // ---------- epilogue: bias + relu, fp32 or fp16 stores ----------
    const int colq = (lane & 3) * 2;
    const int rquad = lane >> 2;
    const size_t row0 = rowBase + wm * 16 + rquad;
#pragma unroll
    for (int nt = 0; nt < 19; ++nt) {
        const int col = wn * 152 + nt * 8 + colq;      // always < 304
        const float2 bv = *(const float2*)(biasp + col);
        float2 v01, v23;
        v01.x = acc[nt][0] + bv.x;
        v01.y = acc[nt][1] + bv.y;
        v23.x = acc[nt][2] + bv.x;
        v23.y = acc[nt][3] + bv.y;
        if (doRelu) {
            v01.x = fmaxf(v01.x, 0.f); v01.y = fmaxf(v01.y, 0.f);
            v23.x = fmaxf(v23.x, 0.f); v23.y = fmaxf(v23.y, 0.f);
        }
        const size_t o0 = row0 * NPS + col;
        const size_t o1 = (row0 + 8) * NPS + col;
        if (outHalf) {
            __half* Ch = (__half*)C;
            *(__half2*)(Ch + o0) = __float22half2_rn(v01);
            *(__half2*)(Ch + o1) = __float22half2_rn(v23);
        } else {
            *(float2*)(C + o0) = v01;
            *(float2*)(C + o1) = v23;
            if (C2) {
                *(float2*)(C2 + o0) = v01;
                *(float2*)(C2 + o1) = v23;
            }
        }
    }
}

// ============ fused prepack: weights + biases + out zero ============
#define SZ_N (NP * 64)
#define SZ_E (NP * 32)
#define SZ_M (NP * 320)
#define PACK_W (SZ_N + SZ_E + 6 * SZ_M + 8 * NP)
#define PACK_TOTAL (PACK_W + 2 * BB * HH)

__global__ __launch_bounds__(256) void pack_all_kernel(
    const float* __restrict__ Wn, const float* __restrict__ We,
    const float* __restrict__ W1, const float* __restrict__ W2,
    const float* __restrict__ bn, const float* __restrict__ be,
    const float* __restrict__ b1, const float* __restrict__ b2,
    float* __restrict__ outAcc)
{
    int idx = blockIdx.x * 256 + threadIdx.x;
    if (idx >= PACK_TOTAL) return;
    if (idx >= PACK_W) {                  // zero r_sum/p_sum region
        outAcc[idx - PACK_W] = 0.f;
        return;
    }

    const float* W; __nv_bfloat16 *Whi, *Wlo; int Kin, Kp;
    if (idx < SZ_N) {
        W = Wn; Whi = g_Wnhi; Wlo = g_Wnlo; Kin = NODE_IN; Kp = 64;
    } else if ((idx -= SZ_N) < SZ_E) {
        W = We; Whi = g_Wehi; Wlo = g_Welo; Kin = EDGE_IN; Kp = 32;
    } else if ((idx -= SZ_E) < 3 * SZ_M) {
        const int l = idx / SZ_M; idx -= l * SZ_M;
        W = W1 + (size_t)l * HH * HH;
        Whi = g_W1hi + (size_t)l * SZ_M; Wlo = g_W1lo + (size_t)l * SZ_M;
        Kin = HH; Kp = 320;
    } else if ((idx -= 3 * SZ_M) < 3 * SZ_M) {
        const int l = idx / SZ_M; idx -= l * SZ_M;
        W = W2 + (size_t)l * HH * HH;
        Whi = g_W2hi + (size_t)l * SZ_M; Wlo = g_W2lo + (size_t)l * SZ_M;
        Kin = HH; Kp = 320;
    } else {
        idx -= 3 * SZ_M;
        const int which = idx / NP;
        const int n = idx - which * NP;
        const float* src = (which == 0) ? bn
                         : (which == 1) ? be
                         : (which < 5)  ? b1 + (size_t)(which - 2) * HH
                                        : b2 + (size_t)(which - 5) * HH;
        g_biasp[idx] = (n < HH) ? src[n] : 0.f;
        return;
    }
    const int n = idx / Kp;
    const int k = idx - n * Kp;
    float v = 0.f;
    if (k < Kin && n < HH) v = W[(size_t)k * HH + n];
    __nv_bfloat16 h = __float2bfloat16_rn(v);
    Whi[idx] = h;
    Wlo[idx] = __float2bfloat16_rn(v - __bfloat162float(h));
}

// ============ message: z[dst] += relu(h[src] + ef), thread = edge x 8 cols ============
__global__ __launch_bounds__(128) void message_kernel(
    const float* __restrict__ h, const __half* __restrict__ ef,
    const int* __restrict__ src, const int* __restrict__ dst,
    float* __restrict__ z)
{
    const int idx = blockIdx.x * 128 + threadIdx.x;
    if (idx >= NE * 38) return;
    const int e = idx / 38;
    const int q = (idx - e * 38) << 3;
    const int s = __ldg(src + e);
    const int d = __ldg(dst + e);
    const float4* hp = (const float4*)(h + (size_t)s * NPS + q);
    const __half2* ep = (const __half2*)(ef + (size_t)e * NPS + q);
    const float4 h0 = hp[0], h1 = hp[1];
    const float2 e0 = __half22float2(ep[0]);
    const float2 e1 = __half22float2(ep[1]);
    const float2 e2 = __half22float2(ep[2]);
    const float2 e3 = __half22float2(ep[3]);
    float* zp = z + (size_t)d * NPS + q;
    const float m0 = fmaxf(h0.x + e0.x, 0.f);
    const float m1 = fmaxf(h0.y + e0.y, 0.f);
    const float m2 = fmaxf(h0.z + e1.x, 0.f);
    const float m3 = fmaxf(h0.w + e1.y, 0.f);
    if (m0 + m1 + m2 + m3 > 0.f) REDV4(zp, m0, m1, m2, m3);
    const float m4 = fmaxf(h1.x + e2.x, 0.f);
    const float m5 = fmaxf(h1.y + e2.y, 0.f);
    const float m6 = fmaxf(h1.z + e3.x, 0.f);
    const float m7 = fmaxf(h1.w + e3.y, 0.f);
    if (m4 + m5 + m6 + m7 > 0.f) REDV4(zp + 4, m4, m5, m6, m7);
}

// ============ pool: out[seg[n]] += h[n] — run-compressed atomics ============
__global__ __launch_bounds__(128) void pool_kernel(
    const float* __restrict__ h, const int* __restrict__ seg,
    float* __restrict__ out)
{
    const int wid  = threadIdx.x >> 5;
    const int lane = threadIdx.x & 31;
    const int n0   = (blockIdx.x * 4 + wid) * 32;
    const int col  = blockIdx.y * 32 + lane;
    const bool act = col < HH;

    float v[32];
    int   sg[32];
#pragma unroll
    for (int i = 0; i < 32; ++i) {
        v[i]  = act ? __ldg(h + (size_t)(n0 + i) * NPS + col) : 0.f;
        sg[i] = __ldg(seg + n0 + i);
    }
    float acc = 0.f;
#pragma unroll
    for (int i = 0; i < 32; ++i) {
        acc += v[i];
        if ((i == 31) || (sg[i + 1 <= 31 ? i + 1 : 31] != sg[i])) {
            if (act) atomicAdd(out + (size_t)sg[i] * HH + col, acc);
            acc = 0.f;
        }
    }
}

__global__ __launch_bounds__(256) void diff_kernel(float* __restrict__ out)
{
    const int idx = blockIdx.x * blockDim.x + threadIdx.x;
    const int BH = BB * HH;
    if (idx < BH) out[idx] = out[BH + idx] - out[2 * BH + idx];
}

// ============================== host orchestration ==============================
static void run_gin(cudaStream_t st, int si,
                    const float* x, const float* e,
                    const int* src, const int* dst, const int* seg,
                    __nv_bfloat16* Wnhi, __nv_bfloat16* Wnlo,
                    __nv_bfloat16* Wehi, __nv_bfloat16* Welo,
                    __nv_bfloat16* W1hi, __nv_bfloat16* W1lo,
                    __nv_bfloat16* W2hi, __nv_bfloat16* W2lo,
                    float* biasp,
                    float* hB, __half* efB, float* zB, float* tB,
                    float* outPart)
{
    float*  h  = hB  + (size_t)si * NN * NPS;
    __half* ef = efB + (size_t)si * NE * NPS;
    float*  z  = zB  + (size_t)si * NN * NPS;
    float*  t  = tB  + (size_t)si * NN * NPS;

    gemm_tc<<<NN / 128, 512, SMEM_BYTES, st>>>(x, Wnhi, Wnlo, biasp, h, z,
                                               NODE_IN, NODE_IN, 2, 1, 0);
    gemm_tc<<<NE / 128, 512, SMEM_BYTES, st>>>(e, Wehi, Welo, biasp + NP,
                                               (float*)ef, nullptr,
                                               EDGE_IN, EDGE_IN, 1, 0, 1);

    for (int l = 0; l < 3; l++) {
        message_kernel<<<NE * 38 / 128, 128, 0, st>>>(h, ef, src, dst, z);
        gemm_tc<<<NN / 128, 512, SMEM_BYTES, st>>>(
            z, W1hi + (size_t)l * NP * 320, W1lo + (size_t)l * NP * 320,
            biasp + (size_t)(2 + l) * NP, t, nullptr, NPS, NPS, 10, 1, 0);
        gemm_tc<<<NN / 128, 512, SMEM_BYTES, st>>>(
            t, W2hi + (size_t)l * NP * 320, W2lo + (size_t)l * NP * 320,
            biasp + (size_t)(5 + l) * NP, h, (l < 2) ? z : nullptr,
            NPS, NPS, 10, (l < 2) ? 1 : 0, 0);
    }
    const dim3 gP(NN / 32 / 4, 10);
    pool_kernel<<<gP, 128, 0, st>>>(h, seg, outPart);
}

extern "C" void kernel_launch(void* const* d_in, const int* in_sizes, int n_in,
                              void* d_out, int out_size)
{
    const float* r_x = (const float*)d_in[0];
    const float* r_e = (const float*)d_in[1];
    const float* p_x = (const float*)d_in[2];
    const float* p_e = (const float*)d_in[3];
    const float* Wn  = (const float*)d_in[4];
    const float* bn  = (const float*)d_in[5];
    const float* We  = (const float*)d_in[6];
    const float* be  = (const float*)d_in[7];
    const float* W1  = (const float*)d_in[8];
    const float* b1  = (const float*)d_in[9];
    const float* W2  = (const float*)d_in[10];
    const float* b2  = (const float*)d_in[11];
    const int* r_src = (const int*)d_in[12];
    const int* r_dst = (const int*)d_in[13];
    const int* r_seg = (const int*)d_in[14];
    const int* p_src = (const int*)d_in[15];
    const int* p_dst = (const int*)d_in[16];
    const int* p_seg = (const int*)d_in[17];

    float* out   = (float*)d_out;
    float* r_sum = out + (size_t)BB * HH;
    float* p_sum = out + (size_t)2 * BB * HH;

    float *h, *z, *t, *biasp;
    __half* ef;
    __nv_bfloat16 *Wnhi, *Wnlo, *Wehi, *Welo, *W1hi, *W1lo, *W2hi, *W2lo;
    cudaGetSymbolAddress((void**)&h,    g_h);
    cudaGetSymbolAddress((void**)&ef,   g_ef);
    cudaGetSymbolAddress((void**)&z,    g_z);
    cudaGetSymbolAddress((void**)&t,    g_t);
    cudaGetSymbolAddress((void**)&Wnhi, g_Wnhi);
    cudaGetSymbolAddress((void**)&Wnlo, g_Wnlo);
    cudaGetSymbolAddress((void**)&Wehi, g_Wehi);
    cudaGetSymbolAddress((void**)&Welo, g_Welo);
    cudaGetSymbolAddress((void**)&W1hi, g_W1hi);
    cudaGetSymbolAddress((void**)&W1lo, g_W1lo);
    cudaGetSymbolAddress((void**)&W2hi, g_W2hi);
    cudaGetSymbolAddress((void**)&W2lo, g_W2lo);
    cudaGetSymbolAddress((void**)&biasp, g_biasp);

    // one-time resources (streams/events; no device memory)
    static cudaStream_t s1 = nullptr, s2 = nullptr;
    static cudaEvent_t evF = nullptr, ev1 = nullptr, ev2 = nullptr;
    if (!s1) {
        cudaStreamCreateWithFlags(&s1, cudaStreamNonBlocking);
        cudaStreamCreateWithFlags(&s2, cudaStreamNonBlocking);
        cudaEventCreateWithFlags(&evF, cudaEventDisableTiming);
        cudaEventCreateWithFlags(&ev1, cudaEventDisableTiming);
        cudaEventCreateWithFlags(&ev2, cudaEventDisableTiming);
        cudaFuncSetAttribute(gemm_tc, cudaFuncAttributeMaxDynamicSharedMemorySize,
                             SMEM_BYTES);
    }

    // launch 0 (capture stream): fused prepack + zero of r_sum/p_sum
    pack_all_kernel<<<(PACK_TOTAL + 255) / 256, 256>>>(Wn, We, W1, W2,
                                                       bn, be, b1, b2, r_sum);
    // simultaneous fork (stagger falsified twice — reverted)
    cudaEventRecord(evF, 0);
    cudaStreamWaitEvent(s1, evF, 0);
    cudaStreamWaitEvent(s2, evF, 0);

    run_gin((cudaStream_t)0, 0,
            r_x, r_e, r_src, r_dst, r_seg,
            Wnhi, Wnlo, Wehi, Welo, W1hi, W1lo, W2hi, W2lo, biasp,
            h, ef, z, t, r_sum);
    run_gin(s1, 1,
            r_x + (size_t)NN * NODE_IN, r_e + (size_t)NE * EDGE_IN,
            r_src + NE, r_dst + NE, r_seg + NN,
            Wnhi, Wnlo, Wehi, Welo, W1hi, W1lo, W2hi, W2lo, biasp,
            h, ef, z, t, r_sum);
    run_gin(s2, 2,
            p_x, p_e, p_src, p_dst, p_seg,
            Wnhi, Wnlo, Wehi, Welo, W1hi, W1lo, W2hi, W2lo, biasp,
            h, ef, z, t, p_sum);

    // join: diff waits on all three
    cudaEventRecord(ev1, s1);
    cudaEventRecord(ev2, s2);
    cudaStreamWaitEvent((cudaStream_t)0, ev1, 0);
    cudaStreamWaitEvent((cudaStream_t)0, ev2, 0);

    diff_kernel<<<(BB * HH + 255) / 256, 256>>>(out);
}